// round 1
// baseline (speedup 1.0000x reference)
#include <cuda_runtime.h>
#include <math.h>

// Problem constants
constexpr int B  = 2;
constexpr int S  = 2048;
constexpr int D  = 1024;
constexpr int H  = 16;
constexpr int HD = 64;
constexpr int M  = B * S;   // 4096 rows for all projection GEMMs

// Scratch (device globals: no allocation allowed in kernel_launch)
__device__ float g_q[(size_t)B * H * S * HD];    // [B,H,S,HD]
__device__ float g_k[(size_t)B * H * S * HD];
__device__ float g_v[(size_t)B * H * S * HD];
__device__ float g_attn[(size_t)B * S * D];      // [B,S,D] attention output (heads concatenated)

// ---------------------------------------------------------------------------
// SGEMM: C = A[M,K] * W[N,K]^T + bias[N]
// MODE 0: C row-major [M,N]
// MODE 1: scatter to q/k/v layout [B,H,S,HD] with m=b*S+s, n=h*HD+e
// 128x128 block tile, BK=8, 256 threads, 8x8 per-thread microtile.
// ---------------------------------------------------------------------------
template <int MODE>
__global__ __launch_bounds__(256)
void sgemm_bias_kernel(const float* __restrict__ A,
                       const float* __restrict__ W,
                       const float* __restrict__ bias,
                       float* __restrict__ C)
{
    constexpr int K = D;
    constexpr int N = D;
    __shared__ float As[8][132];   // transposed tiles, padded stride 132 (conflict-free)
    __shared__ float Bs[8][132];

    const int t  = threadIdx.x;
    const int bm = blockIdx.y * 128;
    const int bn = blockIdx.x * 128;
    const int ty = t >> 4;         // 0..15
    const int tx = t & 15;         // 0..15
    const int lrow = t >> 1;       // 0..127  (tile row for loads)
    const int lk   = (t & 1) << 2; // 0 or 4  (k offset for loads)

    const float* Ap = A + (size_t)(bm + lrow) * K + lk;
    const float* Wp = W + (size_t)(bn + lrow) * K + lk;

    float acc[8][8];
#pragma unroll
    for (int i = 0; i < 8; i++)
#pragma unroll
        for (int j = 0; j < 8; j++) acc[i][j] = 0.f;

    for (int k0 = 0; k0 < K; k0 += 8) {
        const float4 av = *(const float4*)(Ap + k0);
        const float4 wv = *(const float4*)(Wp + k0);
        As[lk + 0][lrow] = av.x; As[lk + 1][lrow] = av.y;
        As[lk + 2][lrow] = av.z; As[lk + 3][lrow] = av.w;
        Bs[lk + 0][lrow] = wv.x; Bs[lk + 1][lrow] = wv.y;
        Bs[lk + 2][lrow] = wv.z; Bs[lk + 3][lrow] = wv.w;
        __syncthreads();

#pragma unroll
        for (int kk = 0; kk < 8; kk++) {
            const float4 a0 = *(const float4*)&As[kk][ty * 8];
            const float4 a1 = *(const float4*)&As[kk][ty * 8 + 4];
            const float4 b0 = *(const float4*)&Bs[kk][tx * 8];
            const float4 b1 = *(const float4*)&Bs[kk][tx * 8 + 4];
            const float ar[8] = {a0.x, a0.y, a0.z, a0.w, a1.x, a1.y, a1.z, a1.w};
            const float br[8] = {b0.x, b0.y, b0.z, b0.w, b1.x, b1.y, b1.z, b1.w};
#pragma unroll
            for (int i = 0; i < 8; i++)
#pragma unroll
                for (int j = 0; j < 8; j++)
                    acc[i][j] += ar[i] * br[j];
        }
        __syncthreads();
    }

#pragma unroll
    for (int i = 0; i < 8; i++) {
        const int m = bm + ty * 8 + i;
#pragma unroll
        for (int j = 0; j < 8; j++) {
            const int n   = bn + tx * 8 + j;
            const float val = acc[i][j] + bias[n];
            if (MODE == 0) {
                C[(size_t)m * N + n] = val;
            } else {
                const int bb = m >> 11;          // m / S
                const int ss = m & (S - 1);
                const int hh = n >> 6;           // n / HD
                const int ee = n & (HD - 1);
                C[(((size_t)bb * H + hh) * S + ss) * HD + ee] = val;
            }
        }
    }
}

// ---------------------------------------------------------------------------
// Flash-attention (fp32): per (b,h) head, 64-row Q tile per CTA, loop over
// 64-row KV tiles with online softmax. 256 threads: 4 threads per Q row,
// each owning 16 score columns and 16 output head-dims.
// Dynamic smem: Qs,Ks,Vs,Ps each [64][68] floats = 69632 bytes.
// ---------------------------------------------------------------------------
__global__ __launch_bounds__(256)
void attn_kernel(const float* __restrict__ q,
                 const float* __restrict__ k,
                 const float* __restrict__ v,
                 float* __restrict__ out)
{
    extern __shared__ float sm[];
    float* Qs = sm;                // 64 x 68
    float* Ks = Qs + 64 * 68;
    float* Vs = Ks + 64 * 68;
    float* Ps = Vs + 64 * 68;

    const int t  = threadIdx.x;
    const int mt = blockIdx.x;
    const int h  = blockIdx.y;
    const int b  = blockIdx.z;
    const size_t base = ((size_t)b * H + h) * S * HD;
    const float* qb = q + base;
    const float* kb = k + base;
    const float* vb = v + base;
    const int m0 = mt * 64;

    // Load Q tile
#pragma unroll
    for (int i = 0; i < 4; i++) {
        const int f  = t + i * 256;
        const int r  = f >> 4;
        const int e4 = (f & 15) << 2;
        *(float4*)&Qs[r * 68 + e4] =
            *(const float4*)&qb[(size_t)(m0 + r) * HD + e4];
    }

    const int r  = t >> 2;     // Q row (0..63)
    const int g  = t & 3;      // quarter within the row
    const int c0 = g << 4;     // 16-col / 16-dim segment start

    float m_i = -1e30f, l_i = 0.f;
    float acc[16];
#pragma unroll
    for (int i = 0; i < 16; i++) acc[i] = 0.f;
    __syncthreads();

    for (int kt = 0; kt < S / 64; kt++) {
        const int n0 = kt * 64;
#pragma unroll
        for (int i = 0; i < 4; i++) {
            const int f  = t + i * 256;
            const int rr = f >> 4;
            const int e4 = (f & 15) << 2;
            *(float4*)&Ks[rr * 68 + e4] =
                *(const float4*)&kb[(size_t)(n0 + rr) * HD + e4];
            *(float4*)&Vs[rr * 68 + e4] =
                *(const float4*)&vb[(size_t)(n0 + rr) * HD + e4];
        }
        __syncthreads();

        // Scores: sv[ci] = Q[r,:] . K[c0+ci,:]
        float sv[16];
#pragma unroll
        for (int ci = 0; ci < 16; ci++) sv[ci] = 0.f;
#pragma unroll
        for (int e4 = 0; e4 < HD; e4 += 4) {
            const float4 qv = *(const float4*)&Qs[r * 68 + e4];
#pragma unroll
            for (int ci = 0; ci < 16; ci++) {
                const float4 kv = *(const float4*)&Ks[(c0 + ci) * 68 + e4];
                sv[ci] += qv.x * kv.x + qv.y * kv.y + qv.z * kv.z + qv.w * kv.w;
            }
        }

        // Online softmax (scale = 1/sqrt(64) = 0.125)
        float mtile = -1e30f;
#pragma unroll
        for (int ci = 0; ci < 16; ci++) {
            sv[ci] *= 0.125f;
            mtile = fmaxf(mtile, sv[ci]);
        }
        mtile = fmaxf(mtile, __shfl_xor_sync(0xffffffffu, mtile, 1));
        mtile = fmaxf(mtile, __shfl_xor_sync(0xffffffffu, mtile, 2));
        const float mnew = fmaxf(m_i, mtile);

        float lt = 0.f;
#pragma unroll
        for (int ci = 0; ci < 16; ci++) {
            sv[ci] = __expf(sv[ci] - mnew);
            lt += sv[ci];
        }
        lt += __shfl_xor_sync(0xffffffffu, lt, 1);
        lt += __shfl_xor_sync(0xffffffffu, lt, 2);

        const float corr = __expf(m_i - mnew);
        l_i = l_i * corr + lt;
        m_i = mnew;
#pragma unroll
        for (int i = 0; i < 16; i++) acc[i] *= corr;

#pragma unroll
        for (int ci = 0; ci < 16; ci++) Ps[r * 68 + c0 + ci] = sv[ci];
        __syncwarp();   // P row is produced by the 4 lanes of this row (same warp)

        // O update: acc[e] += sum_c P[r,c] * V[c, c0+e]
#pragma unroll 4
        for (int c = 0; c < 64; c++) {
            const float p = Ps[r * 68 + c];
            const float4 v0 = *(const float4*)&Vs[c * 68 + c0];
            const float4 v1 = *(const float4*)&Vs[c * 68 + c0 + 4];
            const float4 v2 = *(const float4*)&Vs[c * 68 + c0 + 8];
            const float4 v3 = *(const float4*)&Vs[c * 68 + c0 + 12];
            acc[0]  += p * v0.x; acc[1]  += p * v0.y; acc[2]  += p * v0.z; acc[3]  += p * v0.w;
            acc[4]  += p * v1.x; acc[5]  += p * v1.y; acc[6]  += p * v1.z; acc[7]  += p * v1.w;
            acc[8]  += p * v2.x; acc[9]  += p * v2.y; acc[10] += p * v2.z; acc[11] += p * v2.w;
            acc[12] += p * v3.x; acc[13] += p * v3.y; acc[14] += p * v3.z; acc[15] += p * v3.w;
        }
        __syncthreads();
    }

    const float inv = 1.f / l_i;
    float* ob = out + ((size_t)b * S + m0 + r) * D + h * HD + c0;
#pragma unroll
    for (int i = 0; i < 4; i++) {
        float4 o;
        o.x = acc[i * 4 + 0] * inv;
        o.y = acc[i * 4 + 1] * inv;
        o.z = acc[i * 4 + 2] * inv;
        o.w = acc[i * 4 + 3] * inv;
        *(float4*)&ob[i * 4] = o;
    }
}

// ---------------------------------------------------------------------------
// Launch
// ---------------------------------------------------------------------------
extern "C" void kernel_launch(void* const* d_in, const int* in_sizes, int n_in,
                              void* d_out, int out_size)
{
    const float* x  = (const float*)d_in[0];
    const float* Wq = (const float*)d_in[1];
    const float* bq = (const float*)d_in[2];
    const float* Wk = (const float*)d_in[3];
    const float* bk = (const float*)d_in[4];
    const float* Wv = (const float*)d_in[5];
    const float* bv = (const float*)d_in[6];
    const float* Wp = (const float*)d_in[7];
    const float* bp = (const float*)d_in[8];
    float* out = (float*)d_out;

    float *q, *k, *v, *attn;
    cudaGetSymbolAddress((void**)&q,    g_q);
    cudaGetSymbolAddress((void**)&k,    g_k);
    cudaGetSymbolAddress((void**)&v,    g_v);
    cudaGetSymbolAddress((void**)&attn, g_attn);

    const int smem_attn = 4 * 64 * 68 * (int)sizeof(float);   // 69632 B
    cudaFuncSetAttribute(attn_kernel,
                         cudaFuncAttributeMaxDynamicSharedMemorySize, smem_attn);

    const dim3 ggrid(D / 128, M / 128);   // (8, 32)

    sgemm_bias_kernel<1><<<ggrid, 256>>>(x, Wq, bq, q);
    sgemm_bias_kernel<1><<<ggrid, 256>>>(x, Wk, bk, k);
    sgemm_bias_kernel<1><<<ggrid, 256>>>(x, Wv, bv, v);
    attn_kernel<<<dim3(S / 64, H, B), 256, smem_attn>>>(q, k, v, attn);
    sgemm_bias_kernel<0><<<ggrid, 256>>>(attn, Wp, bp, out);
}

// round 2
// speedup vs baseline: 10.7777x; 10.7777x over previous
#include <cuda_runtime.h>
#include <stdint.h>
#include <math.h>

// Problem constants
constexpr int B  = 2;
constexpr int S  = 2048;
constexpr int D  = 1024;
constexpr int H  = 16;
constexpr int HD = 64;
constexpr int M  = B * S;   // 4096

// Scratch (device globals — no allocation allowed)
__device__ float g_q[(size_t)B * H * S * HD];
__device__ float g_k[(size_t)B * H * S * HD];
__device__ float g_v[(size_t)B * H * S * HD];
__device__ float g_attn[(size_t)B * S * D];

__device__ __forceinline__ uint32_t f2tf(float f) {
    uint32_t u;
    asm("cvt.rna.tf32.f32 %0, %1;" : "=r"(u) : "f"(f));
    return u;
}

__device__ __forceinline__ void mma8(float* c,
                                     uint32_t a0, uint32_t a1, uint32_t a2, uint32_t a3,
                                     uint32_t b0, uint32_t b1) {
    asm volatile(
        "mma.sync.aligned.m16n8k8.row.col.f32.tf32.tf32.f32 "
        "{%0,%1,%2,%3},{%4,%5,%6,%7},{%8,%9},{%0,%1,%2,%3};"
        : "+f"(c[0]), "+f"(c[1]), "+f"(c[2]), "+f"(c[3])
        : "r"(a0), "r"(a1), "r"(a2), "r"(a3), "r"(b0), "r"(b1));
}

// ---------------------------------------------------------------------------
// TF32 tensor-core GEMM: C = A[M,1024] * W[1024,1024]^T + bias
// Block 128x128, BK=16, 8 warps, warp tile 64x32 (4x4 m16n8k8 tiles).
// MODE 0: row-major out [M,N].  MODE 1: scatter to [B,H,S,HD].
// MODE 2: QKV fused — blockIdx.z selects (Wq,bq,g_q)/(Wk,..)/(Wv,..), scatter.
// ---------------------------------------------------------------------------
constexpr int GLDA = 20;  // smem stride (floats): (20*gid + tig) % 32 distinct

template <int MODE>
__global__ __launch_bounds__(256)
void gemm_tc(const float* __restrict__ A,
             const float* __restrict__ W0, const float* __restrict__ b0_,
             const float* __restrict__ W1, const float* __restrict__ b1_,
             const float* __restrict__ W2, const float* __restrict__ b2_,
             float* __restrict__ C0, float* __restrict__ C1, float* __restrict__ C2)
{
    constexpr int K = 1024;
    constexpr int N = 1024;
    constexpr int BK = 16;
    constexpr int NKB = K / BK;

    const float* W;
    const float* bias;
    float* C;
    if (MODE != 2) { W = W0; bias = b0_; C = C0; }
    else {
        const int z = blockIdx.z;
        W    = (z == 0) ? W0 : (z == 1) ? W1 : W2;
        bias = (z == 0) ? b0_ : (z == 1) ? b1_ : b2_;
        C    = (z == 0) ? C0 : (z == 1) ? C1 : C2;
    }

    extern __shared__ uint32_t smg[];
    uint32_t* As = smg;                    // [2][128][GLDA]
    uint32_t* Bs = smg + 2 * 128 * GLDA;   // [2][128][GLDA]

    const int t    = threadIdx.x;
    const int lane = t & 31;
    const int warp = t >> 5;
    const int gid  = lane >> 2;
    const int tig  = lane & 3;
    const int wm   = warp >> 2;   // 0..1 -> m offset wm*64
    const int wn   = warp & 3;    // 0..3 -> n offset wn*32
    const int bm   = blockIdx.y * 128;
    const int bn   = blockIdx.x * 128;

    // staging: 2 float4 per thread for A and for W
    float4 pa[2], pb[2];
    const int sr[2] = { t >> 2, (t + 256) >> 2 };
    const int sc    = (t & 3) * 4;

#define LDG_TILE(kb)                                                          \
    {                                                                         \
        _Pragma("unroll")                                                     \
        for (int i = 0; i < 2; i++) {                                         \
            pa[i] = *(const float4*)&A[(size_t)(bm + sr[i]) * K + (kb) * BK + sc]; \
            pb[i] = *(const float4*)&W[(size_t)(bn + sr[i]) * K + (kb) * BK + sc]; \
        }                                                                     \
    }
#define STS_TILE(buf)                                                         \
    {                                                                         \
        _Pragma("unroll")                                                     \
        for (int i = 0; i < 2; i++) {                                         \
            uint32_t* ap = &As[(buf) * 128 * GLDA + sr[i] * GLDA + sc];       \
            ap[0] = f2tf(pa[i].x); ap[1] = f2tf(pa[i].y);                     \
            ap[2] = f2tf(pa[i].z); ap[3] = f2tf(pa[i].w);                     \
            uint32_t* bp = &Bs[(buf) * 128 * GLDA + sr[i] * GLDA + sc];       \
            bp[0] = f2tf(pb[i].x); bp[1] = f2tf(pb[i].y);                     \
            bp[2] = f2tf(pb[i].z); bp[3] = f2tf(pb[i].w);                     \
        }                                                                     \
    }

    float acc[4][4][4];
#pragma unroll
    for (int i = 0; i < 4; i++)
#pragma unroll
        for (int j = 0; j < 4; j++)
#pragma unroll
            for (int l = 0; l < 4; l++) acc[i][j][l] = 0.f;

    LDG_TILE(0);
    STS_TILE(0);
    __syncthreads();

    for (int kb = 0; kb < NKB; kb++) {
        if (kb + 1 < NKB) LDG_TILE(kb + 1);
        const uint32_t* Ab = &As[(kb & 1) * 128 * GLDA];
        const uint32_t* Bb = &Bs[(kb & 1) * 128 * GLDA];
#pragma unroll
        for (int ks = 0; ks < 2; ks++) {
            uint32_t af[4][4], bf[4][2];
            const int kc = ks * 8 + tig;
#pragma unroll
            for (int mt = 0; mt < 4; mt++) {
                const int r = wm * 64 + mt * 16 + gid;
                af[mt][0] = Ab[r * GLDA + kc];
                af[mt][1] = Ab[(r + 8) * GLDA + kc];
                af[mt][2] = Ab[r * GLDA + kc + 4];
                af[mt][3] = Ab[(r + 8) * GLDA + kc + 4];
            }
#pragma unroll
            for (int nt = 0; nt < 4; nt++) {
                const int n = wn * 32 + nt * 8 + gid;
                bf[nt][0] = Bb[n * GLDA + kc];
                bf[nt][1] = Bb[n * GLDA + kc + 4];
            }
#pragma unroll
            for (int mt = 0; mt < 4; mt++)
#pragma unroll
                for (int nt = 0; nt < 4; nt++)
                    mma8(acc[mt][nt], af[mt][0], af[mt][1], af[mt][2], af[mt][3],
                         bf[nt][0], bf[nt][1]);
        }
        if (kb + 1 < NKB) STS_TILE((kb + 1) & 1);
        __syncthreads();
    }

    // epilogue
#pragma unroll
    for (int mt = 0; mt < 4; mt++) {
        const int r1 = bm + wm * 64 + mt * 16 + gid;
        const int r2 = r1 + 8;
#pragma unroll
        for (int nt = 0; nt < 4; nt++) {
            const int n = bn + wn * 32 + nt * 8 + 2 * tig;
            const float bx = bias[n], by = bias[n + 1];
            float2 v1 = make_float2(acc[mt][nt][0] + bx, acc[mt][nt][1] + by);
            float2 v2 = make_float2(acc[mt][nt][2] + bx, acc[mt][nt][3] + by);
            if (MODE == 0) {
                *(float2*)&C[(size_t)r1 * N + n] = v1;
                *(float2*)&C[(size_t)r2 * N + n] = v2;
            } else {
                const int hh = n >> 6, ee = n & 63;
                const int b1r = r1 >> 11, s1r = r1 & (S - 1);
                const int b2r = r2 >> 11, s2r = r2 & (S - 1);
                *(float2*)&C[(((size_t)b1r * H + hh) * S + s1r) * HD + ee] = v1;
                *(float2*)&C[(((size_t)b2r * H + hh) * S + s2r) * HD + ee] = v2;
            }
        }
    }
#undef LDG_TILE
#undef STS_TILE
}

// ---------------------------------------------------------------------------
// TF32 tensor-core flash attention.
// CTA = (64 Q rows, one (b,h)). 4 warps, warp owns 16 Q rows.
// Online softmax entirely in registers using documented C-fragment layout.
// ---------------------------------------------------------------------------
__global__ __launch_bounds__(128)
void attn_tc(const float* __restrict__ q,
             const float* __restrict__ k,
             const float* __restrict__ v,
             float* __restrict__ out)
{
    extern __shared__ uint32_t sma[];
    uint32_t* Qs = sma;               // 64 x 68
    uint32_t* Ks = Qs + 64 * 68;      // 64 x 68
    uint32_t* Vs = Ks + 64 * 68;      // 64 x 72
    uint32_t* Ps = Vs + 64 * 72;      // 64 x 68

    const int t    = threadIdx.x;
    const int lane = t & 31;
    const int warp = t >> 5;          // 0..3
    const int gid  = lane >> 2;
    const int tig  = lane & 3;
    const int rm   = warp * 16;

    const int hb = blockIdx.y, bb = blockIdx.z;
    const int m0 = blockIdx.x * 64;
    const size_t base = ((size_t)bb * H + hb) * S * HD;

    // Stage Q (scaled by 1/sqrt(HD) = 0.125), tf32
#pragma unroll
    for (int i = 0; i < 8; i++) {
        const int f = t + i * 128;
        const int r = f >> 4, c = (f & 15) * 4;
        const float4 qv = *(const float4*)&q[base + (size_t)(m0 + r) * HD + c];
        uint32_t* p = &Qs[r * 68 + c];
        p[0] = f2tf(qv.x * 0.125f); p[1] = f2tf(qv.y * 0.125f);
        p[2] = f2tf(qv.z * 0.125f); p[3] = f2tf(qv.w * 0.125f);
    }
    __syncthreads();

    // Hoist Q fragments into registers (held for the whole KV loop)
    uint32_t qf[8][4];
#pragma unroll
    for (int ks = 0; ks < 8; ks++) {
        const int c = ks * 8 + tig;
        qf[ks][0] = Qs[(rm + gid) * 68 + c];
        qf[ks][1] = Qs[(rm + gid + 8) * 68 + c];
        qf[ks][2] = Qs[(rm + gid) * 68 + c + 4];
        qf[ks][3] = Qs[(rm + gid + 8) * 68 + c + 4];
    }

    float m1 = -1e30f, m2 = -1e30f, l1 = 0.f, l2 = 0.f;
    float o[8][4];
#pragma unroll
    for (int nt = 0; nt < 8; nt++)
#pragma unroll
        for (int j = 0; j < 4; j++) o[nt][j] = 0.f;

    for (int kt = 0; kt < S / 64; kt++) {
        const int n0 = kt * 64;
        // Stage K, V tiles (tf32)
#pragma unroll
        for (int i = 0; i < 8; i++) {
            const int f = t + i * 128;
            const int r = f >> 4, c = (f & 15) * 4;
            const float4 kv = *(const float4*)&k[base + (size_t)(n0 + r) * HD + c];
            uint32_t* pk = &Ks[r * 68 + c];
            pk[0] = f2tf(kv.x); pk[1] = f2tf(kv.y); pk[2] = f2tf(kv.z); pk[3] = f2tf(kv.w);
            const float4 vv = *(const float4*)&v[base + (size_t)(n0 + r) * HD + c];
            uint32_t* pv = &Vs[r * 72 + c];
            pv[0] = f2tf(vv.x); pv[1] = f2tf(vv.y); pv[2] = f2tf(vv.z); pv[3] = f2tf(vv.w);
        }
        __syncthreads();

        // scores = Q . K^T   (warp rows rm..rm+15, all 64 cols)
        float sc[8][4];
#pragma unroll
        for (int nt = 0; nt < 8; nt++)
#pragma unroll
            for (int j = 0; j < 4; j++) sc[nt][j] = 0.f;
#pragma unroll
        for (int ks = 0; ks < 8; ks++) {
            const int c = ks * 8 + tig;
#pragma unroll
            for (int nt = 0; nt < 8; nt++) {
                const uint32_t kb0 = Ks[(nt * 8 + gid) * 68 + c];
                const uint32_t kb1 = Ks[(nt * 8 + gid) * 68 + c + 4];
                mma8(sc[nt], qf[ks][0], qf[ks][1], qf[ks][2], qf[ks][3], kb0, kb1);
            }
        }

        // Online softmax in registers.
        // Row r1 = rm+gid owns sc[*][0..1]; row r2 = r1+8 owns sc[*][2..3].
        float mx1 = -1e30f, mx2 = -1e30f;
#pragma unroll
        for (int nt = 0; nt < 8; nt++) {
            mx1 = fmaxf(mx1, fmaxf(sc[nt][0], sc[nt][1]));
            mx2 = fmaxf(mx2, fmaxf(sc[nt][2], sc[nt][3]));
        }
        mx1 = fmaxf(mx1, __shfl_xor_sync(0xffffffffu, mx1, 1));
        mx1 = fmaxf(mx1, __shfl_xor_sync(0xffffffffu, mx1, 2));
        mx2 = fmaxf(mx2, __shfl_xor_sync(0xffffffffu, mx2, 1));
        mx2 = fmaxf(mx2, __shfl_xor_sync(0xffffffffu, mx2, 2));
        const float M1 = fmaxf(m1, mx1);
        const float M2 = fmaxf(m2, mx2);

        float s1 = 0.f, s2 = 0.f;
#pragma unroll
        for (int nt = 0; nt < 8; nt++) {
            sc[nt][0] = __expf(sc[nt][0] - M1); s1 += sc[nt][0];
            sc[nt][1] = __expf(sc[nt][1] - M1); s1 += sc[nt][1];
            sc[nt][2] = __expf(sc[nt][2] - M2); s2 += sc[nt][2];
            sc[nt][3] = __expf(sc[nt][3] - M2); s2 += sc[nt][3];
        }
        s1 += __shfl_xor_sync(0xffffffffu, s1, 1);
        s1 += __shfl_xor_sync(0xffffffffu, s1, 2);
        s2 += __shfl_xor_sync(0xffffffffu, s2, 1);
        s2 += __shfl_xor_sync(0xffffffffu, s2, 2);

        const float c1 = __expf(m1 - M1);
        const float c2 = __expf(m2 - M2);
        l1 = l1 * c1 + s1;
        l2 = l2 * c2 + s2;
        m1 = M1; m2 = M2;
#pragma unroll
        for (int nt = 0; nt < 8; nt++) {
            o[nt][0] *= c1; o[nt][1] *= c1;
            o[nt][2] *= c2; o[nt][3] *= c2;
        }

        // P -> smem (tf32), only this warp's rows; same warp consumes.
#pragma unroll
        for (int nt = 0; nt < 8; nt++) {
            const int cc = nt * 8 + 2 * tig;
            uint2 w1 = make_uint2(f2tf(sc[nt][0]), f2tf(sc[nt][1]));
            uint2 w2 = make_uint2(f2tf(sc[nt][2]), f2tf(sc[nt][3]));
            *(uint2*)&Ps[(rm + gid) * 68 + cc]     = w1;
            *(uint2*)&Ps[(rm + gid + 8) * 68 + cc] = w2;
        }
        __syncwarp();

        // O += P . V
#pragma unroll
        for (int ks = 0; ks < 8; ks++) {
            const int c = ks * 8 + tig;
            const uint32_t pa0 = Ps[(rm + gid) * 68 + c];
            const uint32_t pa1 = Ps[(rm + gid + 8) * 68 + c];
            const uint32_t pa2 = Ps[(rm + gid) * 68 + c + 4];
            const uint32_t pa3 = Ps[(rm + gid + 8) * 68 + c + 4];
#pragma unroll
            for (int nt = 0; nt < 8; nt++) {
                const uint32_t vb0 = Vs[(ks * 8 + tig) * 72 + nt * 8 + gid];
                const uint32_t vb1 = Vs[(ks * 8 + tig + 4) * 72 + nt * 8 + gid];
                mma8(o[nt], pa0, pa1, pa2, pa3, vb0, vb1);
            }
        }
        __syncthreads();
    }

    // Epilogue: normalize and write [B,S,D] with heads concatenated
    const float i1 = 1.f / l1;
    const float i2 = 1.f / l2;
    const int s1r = m0 + rm + gid;
    const int s2r = s1r + 8;
#pragma unroll
    for (int nt = 0; nt < 8; nt++) {
        const int n = nt * 8 + 2 * tig;
        *(float2*)&out[((size_t)bb * S + s1r) * D + hb * HD + n] =
            make_float2(o[nt][0] * i1, o[nt][1] * i1);
        *(float2*)&out[((size_t)bb * S + s2r) * D + hb * HD + n] =
            make_float2(o[nt][2] * i2, o[nt][3] * i2);
    }
}

// ---------------------------------------------------------------------------
// Launch
// ---------------------------------------------------------------------------
extern "C" void kernel_launch(void* const* d_in, const int* in_sizes, int n_in,
                              void* d_out, int out_size)
{
    const float* x  = (const float*)d_in[0];
    const float* Wq = (const float*)d_in[1];
    const float* bq = (const float*)d_in[2];
    const float* Wk = (const float*)d_in[3];
    const float* bk = (const float*)d_in[4];
    const float* Wv = (const float*)d_in[5];
    const float* bv = (const float*)d_in[6];
    const float* Wp = (const float*)d_in[7];
    const float* bp = (const float*)d_in[8];
    float* out = (float*)d_out;

    float *q, *k, *v, *attn;
    cudaGetSymbolAddress((void**)&q,    g_q);
    cudaGetSymbolAddress((void**)&k,    g_k);
    cudaGetSymbolAddress((void**)&v,    g_v);
    cudaGetSymbolAddress((void**)&attn, g_attn);

    const int smem_gemm = 2 * 2 * 128 * GLDA * (int)sizeof(uint32_t);   // 40960
    const int smem_attn = (64 * 68 * 3 + 64 * 72) * (int)sizeof(uint32_t); // 70656

    static bool attr_set = false;
    if (!attr_set) {
        cudaFuncSetAttribute(attn_tc, cudaFuncAttributeMaxDynamicSharedMemorySize, smem_attn);
        attr_set = true;
    }

    // Fused QKV projections (grid.z selects q/k/v)
    gemm_tc<2><<<dim3(D / 128, M / 128, 3), 256, smem_gemm>>>(
        x, Wq, bq, Wk, bk, Wv, bv, q, k, v);

    // Flash attention
    attn_tc<<<dim3(S / 64, H, B), 128, smem_attn>>>(q, k, v, attn);

    // Output projection
    gemm_tc<0><<<dim3(D / 128, M / 128), 256, smem_gemm>>>(
        attn, Wp, bp, nullptr, nullptr, nullptr, nullptr, out, nullptr, nullptr);
}